// round 11
// baseline (speedup 1.0000x reference)
#include <cuda_runtime.h>

#define F_CH    64
#define HW      4096
#define BATCH   32
#define NSTAT   14
#define GSIZE   32            // blocks per channel (one per batch)
#define FPR     4             // channels in flight per round
#define NBLK    (FPR * GSIZE) // 128 persistent blocks, single wave (<=148 SMs)
#define ITERS   (F_CH / FPR)  // 16 rounds
#define PLANE4  (4 * HW)      // floats per tile buffer (4 planes)

__device__ float g_part[F_CH * GSIZE * NSTAT];
__device__ unsigned int g_cnt[F_CH];   // monotonic tickets (zero-init)

__device__ __forceinline__ unsigned int ld_acq(const unsigned int* p) {
    unsigned int v;
    asm volatile("ld.acquire.gpu.global.u32 %0, [%1];" : "=r"(v) : "l"(p) : "memory");
    return v;
}

__device__ __forceinline__ void acc4(float x0, float x1, float x2, float x3, float* s) {
    s[0] += x0; s[1] += x1; s[2] += x2; s[3] += x3;
    s[4]  = fmaf(x0, x0, s[4]);
    s[5]  = fmaf(x0, x1, s[5]);
    s[6]  = fmaf(x0, x2, s[6]);
    s[7]  = fmaf(x0, x3, s[7]);
    s[8]  = fmaf(x1, x1, s[8]);
    s[9]  = fmaf(x1, x2, s[9]);
    s[10] = fmaf(x1, x3, s[10]);
    s[11] = fmaf(x2, x3, s[11]);
    s[12] = fmaf(x2, x2, s[12]);
    s[13] = fmaf(x3, x3, s[13]);
}
// s: 0..3 sums; 4:00 5:01 6:02 7:03 8:11 9:12 10:13 11:23 12:22 13:33

__device__ __forceinline__ float4 mix4(float4 v0, float4 v1, float4 v2, float4 v3,
                                       float w0, float w1, float w2, float w3, float bb) {
    float4 o;
    o.x = fmaf(w0, v0.x, fmaf(w1, v1.x, fmaf(w2, v2.x, fmaf(w3, v3.x, bb))));
    o.y = fmaf(w0, v0.y, fmaf(w1, v1.y, fmaf(w2, v2.y, fmaf(w3, v3.y, bb))));
    o.z = fmaf(w0, v0.z, fmaf(w1, v1.z, fmaf(w2, v2.z, fmaf(w3, v3.z, bb))));
    o.w = fmaf(w0, v0.w, fmaf(w1, v1.w, fmaf(w2, v2.w, fmaf(w3, v3.w, bb))));
    return o;
}

// Load tile for (f,bb) into smem buffer, accumulate stats, publish partials, arrive.
__device__ __forceinline__ void load_stats_arrive(
    const float* __restrict__ x, int f, int bb, float* __restrict__ buf,
    float (*sm)[NSTAT]) {
    const size_t base = ((size_t)bb * 256 + f) * HW;
    const int i0 = threadIdx.x, i1 = threadIdx.x + 512;

    float s[NSTAT];
#pragma unroll
    for (int k = 0; k < NSTAT; k++) s[k] = 0.f;

#pragma unroll
    for (int rep = 0; rep < 2; rep++) {
        const int i = (rep == 0) ? i0 : i1;
        float4 v0 = __ldcs((const float4*)(x + base) + i);
        float4 v1 = __ldcs((const float4*)(x + base + (size_t)64  * HW) + i);
        float4 v2 = __ldcs((const float4*)(x + base + (size_t)128 * HW) + i);
        float4 v3 = __ldcs((const float4*)(x + base + (size_t)192 * HW) + i);
        acc4(v0.x, v1.x, v2.x, v3.x, s);
        acc4(v0.y, v1.y, v2.y, v3.y, s);
        acc4(v0.z, v1.z, v2.z, v3.z, s);
        acc4(v0.w, v1.w, v2.w, v3.w, s);
        ((float4*)buf)[i]                = v0;
        ((float4*)(buf + HW))[i]         = v1;
        ((float4*)(buf + 2 * HW))[i]     = v2;
        ((float4*)(buf + 3 * HW))[i]     = v3;
    }

#pragma unroll
    for (int k = 0; k < NSTAT; k++) {
#pragma unroll
        for (int off = 16; off; off >>= 1)
            s[k] += __shfl_down_sync(0xffffffffu, s[k], off);
    }
    const int warp = threadIdx.x >> 5, lane = threadIdx.x & 31;
    if (lane == 0) {
#pragma unroll
        for (int k = 0; k < NSTAT; k++) sm[warp][k] = s[k];
    }
    __syncthreads();
    if (threadIdx.x < NSTAT) {
        float t = 0.f;
#pragma unroll
        for (int w = 0; w < 16; w++) t += sm[w][threadIdx.x];
        g_part[(f * GSIZE + bb) * NSTAT + threadIdx.x] = t;
    }
    __syncthreads();
    if (threadIdx.x == 0) {
        __threadfence();                 // release partials
        atomicAdd(&g_cnt[f], 1u);        // arrive (monotonic, replay-safe)
    }
}

__global__ __launch_bounds__(512) void fused_qbn(const float* __restrict__ x,
                                                 const float* __restrict__ weight,
                                                 const float* __restrict__ bias,
                                                 float* __restrict__ out) {
    const int f_loc = blockIdx.x >> 5;   // 0..3
    const int bb    = blockIdx.x & 31;   // 0..31
    extern __shared__ float dyn[];       // 2 x PLANE4 floats (128 KB)
    __shared__ float sm[16][NSTAT];
    __shared__ float AC[20];

    // Per-launch barrier epoch: counters are monotonic across graph replays.
    unsigned int epoch0 = 0;
    if (threadIdx.x == 0) epoch0 = (ld_acq(&g_cnt[f_loc]) / GSIZE) * GSIZE;  // unused; placeholder
    // (epoch handled implicitly: each wait targets  base + (it_round+1)*GSIZE below
    //  via ticket math inside the wait)

    // Prologue: round 0
    load_stats_arrive(x, f_loc, bb, dyn, sm);

    for (int it = 0; it < ITERS; it++) {
        const int f = it * FPR + f_loc;
        float* cur = dyn + (it & 1) * PLANE4;

        // Issue next round's loads BEFORE waiting — hides barrier skew.
        if (it + 1 < ITERS)
            load_stats_arrive(x, (it + 1) * FPR + f_loc, bb, dyn + ((it + 1) & 1) * PLANE4, sm);

        // Wait: counter for f must reach a multiple-of-GSIZE boundary past our arrival.
        if (threadIdx.x == 0) {
            // Our arrival for f was the (something)th ticket; all GSIZE arrivals for
            // this round complete when counter hits the next GSIZE-aligned boundary
            // at or above our ticket+1. Since each f gets exactly GSIZE arrivals per
            // launch, boundary = ceil-to-GSIZE of any ticket in this round.
            unsigned int c;
            do { c = ld_acq(&g_cnt[f]); } while (c % GSIZE != 0u || c == 0u
                    ? (c % GSIZE != 0u) : false);
            // simpler robust form below
        }
        __syncthreads();
        // Robust wait (all threads see it after sync): spin until counter % GSIZE == 0
        // AND counter > 0 for this round. Because each launch adds exactly GSIZE to
        // g_cnt[f], "round complete" == counter divisible by GSIZE after our arrival.
        if (threadIdx.x == 0) {
            while (ld_acq(&g_cnt[f]) % GSIZE != 0u) { }
            __threadfence();
        }
        __syncthreads();

        // Redundant per-block solve for f
        if (threadIdx.x < 32) {
            float r[NSTAT];
            const float* pa = &g_part[(f * GSIZE + threadIdx.x) * NSTAT];
#pragma unroll
            for (int k = 0; k < NSTAT; k++) r[k] = __ldcg(&pa[k]);
#pragma unroll
            for (int k = 0; k < NSTAT; k++) {
#pragma unroll
                for (int off = 16; off; off >>= 1)
                    r[k] += __shfl_down_sync(0xffffffffu, r[k], off);
            }
            if (threadIdx.x == 0) {
                const float invN = 1.0f / (float)(BATCH * HW);
                const float eps = 1e-5f;
                float m0 = r[0] * invN, m1 = r[1] * invN, m2 = r[2] * invN, m3 = r[3] * invN;
                float c00 = r[4]  * invN - m0 * m0 + eps;
                float c10 = r[5]  * invN - m0 * m1;
                float c20 = r[6]  * invN - m0 * m2;
                float c30 = r[7]  * invN - m0 * m3;
                float c11 = r[8]  * invN - m1 * m1 + eps;
                float c21 = r[9]  * invN - m1 * m2;
                float c31 = r[10] * invN - m1 * m3;
                float c32 = r[11] * invN - m2 * m3;
                float c22 = r[12] * invN - m2 * m2 + eps;
                float c33 = r[13] * invN - m3 * m3 + eps;

                float L00 = sqrtf(c00);
                float L10 = c10 / L00, L20 = c20 / L00, L30 = c30 / L00;
                float L11 = sqrtf(c11 - L10 * L10);
                float L21 = (c21 - L20 * L10) / L11;
                float L31 = (c31 - L30 * L10) / L11;
                float L22 = sqrtf(c22 - L20 * L20 - L21 * L21);
                float L32 = (c32 - L30 * L20 - L31 * L21) / L22;
                float L33 = sqrtf(c33 - L30 * L30 - L31 * L31 - L32 * L32);

                float i00f = 1.f / L00, i11f = 1.f / L11, i22f = 1.f / L22, i33f = 1.f / L33;
                float i10f = -(L10 * i00f) * i11f;
                float i20f = -(L20 * i00f + L21 * i10f) * i22f;
                float i21f = -(L21 * i11f) * i22f;
                float i30f = -(L30 * i00f + L31 * i10f + L32 * i20f) * i33f;
                float i31f = -(L31 * i11f + L32 * i21f) * i33f;
                float i32f = -(L32 * i22f) * i33f;

                float Linv[4][4] = {{i00f, 0, 0, 0},
                                    {i10f, i11f, 0, 0},
                                    {i20f, i21f, i22f, 0},
                                    {i30f, i31f, i32f, i33f}};
                float m[4] = {m0, m1, m2, m3};
#pragma unroll
                for (int i = 0; i < 4; i++) {
                    float A[4];
#pragma unroll
                    for (int j = 0; j < 4; j++) {
                        float t2 = 0.f;
#pragma unroll
                        for (int k = 0; k < 4; k++)
                            if (k >= j) t2 = fmaf(weight[(i * 4 + k) * F_CH + f], Linv[k][j], t2);
                        A[j] = t2;
                        AC[i * 4 + j] = t2;
                    }
                    AC[16 + i] = bias[i * F_CH + f]
                               - (A[0] * m[0] + A[1] * m[1] + A[2] * m[2] + A[3] * m[3]);
                }
            }
        }
        __syncthreads();

        // Phase 2: mix from smem tile, store
        float a00 = AC[0],  a01 = AC[1],  a02 = AC[2],  a03 = AC[3];
        float a10 = AC[4],  a11 = AC[5],  a12 = AC[6],  a13 = AC[7];
        float a20 = AC[8],  a21 = AC[9],  a22 = AC[10], a23 = AC[11];
        float a30 = AC[12], a31 = AC[13], a32 = AC[14], a33 = AC[15];
        float k0 = AC[16], k1 = AC[17], k2 = AC[18], k3 = AC[19];

        const size_t base = ((size_t)bb * 256 + f) * HW;
        float4* __restrict__ q0 = (float4*)(out + base);
        float4* __restrict__ q1 = (float4*)(out + base + (size_t)64  * HW);
        float4* __restrict__ q2 = (float4*)(out + base + (size_t)128 * HW);
        float4* __restrict__ q3 = (float4*)(out + base + (size_t)192 * HW);

#pragma unroll
        for (int rep = 0; rep < 2; rep++) {
            const int i = (rep == 0) ? threadIdx.x : threadIdx.x + 512;
            float4 v0 = ((const float4*)cur)[i];
            float4 v1 = ((const float4*)(cur + HW))[i];
            float4 v2 = ((const float4*)(cur + 2 * HW))[i];
            float4 v3 = ((const float4*)(cur + 3 * HW))[i];
            __stcs(q0 + i, mix4(v0, v1, v2, v3, a00, a01, a02, a03, k0));
            __stcs(q1 + i, mix4(v0, v1, v2, v3, a10, a11, a12, a13, k1));
            __stcs(q2 + i, mix4(v0, v1, v2, v3, a20, a21, a22, a23, k2));
            __stcs(q3 + i, mix4(v0, v1, v2, v3, a30, a31, a32, a33, k3));
        }
        __syncthreads();   // buffer/AC reuse safety
    }
}

extern "C" void kernel_launch(void* const* d_in, const int* in_sizes, int n_in,
                              void* d_out, int out_size) {
    const float* x      = (const float*)d_in[0];
    const float* weight = (const float*)d_in[1];
    const float* bias   = (const float*)d_in[2];
    float* out = (float*)d_out;

    static int smem_set = 0;
    if (!smem_set) {
        cudaFuncSetAttribute(fused_qbn, cudaFuncAttributeMaxDynamicSharedMemorySize,
                             2 * PLANE4 * (int)sizeof(float));
        smem_set = 1;
    }
    fused_qbn<<<NBLK, 512, 2 * PLANE4 * sizeof(float)>>>(x, weight, bias, out);
}